// round 13
// baseline (speedup 1.0000x reference)
#include <cuda_runtime.h>
#include <cuda_fp16.h>
#include <cstdint>

// SpatialDeformer3D: trilinear warp of X[...,0] by per-voxel deformation.
// Shapes fixed: B=2, H=160, W=192, D=160.
//
// R12: xz-quad packed fp16 volume.
//   g_quad[i], i = bN + y*WD + x*D + z, holds 4 halves (8 B, always aligned):
//     lo = (v(y,x,z),   v(y,x,z+1))
//     hi = (v(y,x+1,z), v(y,x+1,z+1))
//   One LDG.64 per (voxel, y-level) -> 2 gathers/voxel (was 4 in R8, 8 in R4).
//   Degenerate x or z (floor outside [0,dim-2]) contributes EXACTLY zero in
//   the reference (w0+w1 = clip(hi)-clip(lo) = 0) -> zero weights + safe index.
//   y degeneracy cancels algebraically (same quad loaded twice).
// Def loads: R8's proven __ldcs float2 x3 (TMA staging regressed in R11).

namespace {
constexpr int B  = 2;
constexpr int H  = 160;
constexpr int W  = 192;
constexpr int D  = 160;
constexpr int WD = W * D;            // 30720
constexpr int N  = H * W * D;        // 4,915,200 per batch
constexpr int NT = B * N;            // 9,830,400 total voxels
constexpr int PRE_ITEMS = NT / 8;    // 8 quads (z-run) per pre-pass thread
}

// Quad volume: 8 B per voxel = 78.6 MB. Static scratch (no allocs allowed).
__device__ uint2 g_quad[NT];

// ---------------------------------------------------------------------------
// Pre-pass: build quads. Thread i handles 8 consecutive-z quads of one (b,y,x)
// row. Reads ch0 of rows x and x+1 (second read L2-caught by neighbors).
__global__ void __launch_bounds__(256)
quad_kernel(const float4* __restrict__ X4) {
    int i = blockIdx.x * blockDim.x + threadIdx.x;   // [0, NT/8)
    if (i >= PRE_ITEMS) return;

    int v0  = i * 8;                  // first voxel (global), z..z+7 in one row
    int b   = v0 / N;
    int r   = v0 - b * N;
    int y   = r / WD;
    int rem = r - y * WD;
    int x   = rem / D;
    int z   = rem - x * D;            // multiple of 8

    bool ztail = (z + 8 < D);
    // Row x: 8 ch0 values (+1 lookahead). X interleaved: X4[k] = vox 2k,2k+1.
    int a0 = v0 >> 1;                 // X4 base for row x
    float e[9];
    {
        float4 p0 = X4[a0 + 0], p1 = X4[a0 + 1], p2 = X4[a0 + 2], p3 = X4[a0 + 3];
        e[0]=p0.x; e[1]=p0.z; e[2]=p1.x; e[3]=p1.z;
        e[4]=p2.x; e[5]=p2.z; e[6]=p3.x; e[7]=p3.z;
        e[8] = ztail ? X4[a0 + 4].x : e[7];   // z=D-1 quad is never read
    }
    // Row x+1 (clamped at x=W-1; those quads are never read).
    int v1 = (x + 1 < W) ? v0 + D : v0;
    int a1 = v1 >> 1;
    float f[9];
    {
        float4 p0 = X4[a1 + 0], p1 = X4[a1 + 1], p2 = X4[a1 + 2], p3 = X4[a1 + 3];
        f[0]=p0.x; f[1]=p0.z; f[2]=p1.x; f[3]=p1.z;
        f[4]=p2.x; f[5]=p2.z; f[6]=p3.x; f[7]=p3.z;
        f[8] = ztail ? X4[a1 + 4].x : f[7];
    }

    uint2 q[8];
#pragma unroll
    for (int k = 0; k < 8; ++k) {
        __half2 lo = __floats2half2_rn(e[k], e[k + 1]);
        __half2 hi = __floats2half2_rn(f[k], f[k + 1]);
        q[k].x = *reinterpret_cast<uint32_t*>(&lo);
        q[k].y = *reinterpret_cast<uint32_t*>(&hi);
    }
    // 8 uint2 = 64 B, contiguous + 16B-aligned: 4 uint4 stores.
    uint4* dst = reinterpret_cast<uint4*>(&g_quad[v0]);
    const uint4* src = reinterpret_cast<const uint4*>(q);
    dst[0] = src[0]; dst[1] = src[1]; dst[2] = src[2]; dst[3] = src[3];
}

// ---------------------------------------------------------------------------
__device__ __forceinline__ float clampi_f(int v, int hi, int* out_i) {
    int c = v < 0 ? 0 : (v > hi ? hi : v);
    *out_i = c;
    return (float)c;
}

__device__ __forceinline__ float sample_one(int bN, int ix, int iy, int iz,
                                            float dx, float dy, float dz) {
    float x = (float)ix + dx;
    float y = (float)iy + dy;
    float z = (float)iz + dz;

    int x0i = (int)floorf(x);
    int y0i = (int)floorf(y);
    int z0i = (int)floorf(z);

    // y: clamp both levels; degenerate y cancels algebraically.
    int y0, y1;
    float y0f = clampi_f(y0i,     H - 1, &y0);
    float y1f = clampi_f(y0i + 1, H - 1, &y1);
    float wy0 = y - y0f, wy1 = y1f - y;

    // x/z: quad requires base in [0, dim-2]; outside -> exact zero contribution.
    bool xok  = (x0i >= 0) && (x0i < W - 1);
    int  xc   = xok ? x0i : 0;
    float wx0 = xok ? (x - (float)x0i)        : 0.0f;
    float wx1 = xok ? ((float)x0i + 1.0f - x) : 0.0f;

    bool zok  = (z0i >= 0) && (z0i < D - 1);
    int  zc   = zok ? z0i : 0;
    float wz0 = zok ? (z - (float)z0i)        : 0.0f;
    float wz1 = zok ? ((float)z0i + 1.0f - z) : 0.0f;

    int base = bN + xc * D + zc;
    uint2 q0 = __ldg(&g_quad[base + y0 * WD]);
    uint2 q1 = __ldg(&g_quad[base + y1 * WD]);

    __half2 lo0 = *reinterpret_cast<__half2*>(&q0.x);  // (v(x0,z0), v(x0,z1)) @ y0
    __half2 hi0 = *reinterpret_cast<__half2*>(&q0.y);  // (v(x1,z0), v(x1,z1)) @ y0
    __half2 lo1 = *reinterpret_cast<__half2*>(&q1.x);
    __half2 hi1 = *reinterpret_cast<__half2*>(&q1.y);

    float c00 = wz1 * __half2float(lo0.x) + wz0 * __half2float(lo0.y);
    float c01 = wz1 * __half2float(hi0.x) + wz0 * __half2float(hi0.y);
    float c10 = wz1 * __half2float(lo1.x) + wz0 * __half2float(lo1.y);
    float c11 = wz1 * __half2float(hi1.x) + wz0 * __half2float(hi1.y);

    float c0 = wx1 * c00 + wx0 * c01;   // y0 level
    float c1 = wx1 * c10 + wx0 * c11;   // y1 level

    return wy1 * c0 + wy0 * c1;
}

__global__ void __launch_bounds__(256)
deform3d_kernel(const float2* __restrict__ def2,
                float2* __restrict__ out2) {
    int t = blockIdx.x * blockDim.x + threadIdx.x;  // [0, NT/2)
    if (t >= NT / 2) return;

    int r2  = t * 2;
    int b   = r2 / N;
    int r   = r2 - b * N;
    int iy  = r / WD;
    int rem = r - iy * WD;
    int ix  = rem / D;
    int iz  = rem - ix * D;        // even; iz+1 < D

    float2 d0 = __ldcs(&def2[3 * t + 0]);   // (dxA, dyA)
    float2 d1 = __ldcs(&def2[3 * t + 1]);   // (dzA, dxB)
    float2 d2 = __ldcs(&def2[3 * t + 2]);   // (dyB, dzB)

    int bN = b * N;
    float2 o;
    o.x = sample_one(bN, ix, iy, iz,     d0.x, d0.y, d1.x);
    o.y = sample_one(bN, ix, iy, iz + 1, d1.y, d2.x, d2.y);

    __stcs(&out2[t], o);
}

extern "C" void kernel_launch(void* const* d_in, const int* in_sizes, int n_in,
                              void* d_out, int out_size) {
    const float* X   = (const float*)d_in[0];
    const float* def = (const float*)d_in[1];

    constexpr int threads = 256;
    constexpr int pre_blocks  = (PRE_ITEMS + threads - 1) / threads;   // 4800
    constexpr int main_blocks = (NT / 2 + threads - 1) / threads;      // 19200

    quad_kernel<<<pre_blocks, threads>>>(reinterpret_cast<const float4*>(X));
    deform3d_kernel<<<main_blocks, threads>>>(
        reinterpret_cast<const float2*>(def),
        reinterpret_cast<float2*>(d_out));
}

// round 14
// speedup vs baseline: 1.2638x; 1.2638x over previous
#include <cuda_runtime.h>
#include <cuda_fp16.h>
#include <cstdint>

// SpatialDeformer3D: trilinear warp of X[...,0] by per-voxel deformation.
// Shapes fixed: B=2, H=160, W=192, D=160.
//
// R14: fused pre+main kernel with batch-level producer/consumer overlap.
//  - R8 core (best proven): parity-duplicated fp16 volume, half2 z-pair
//    gathers (4 LDG/vox), __ldcs float2 def loads, float2 out.
//  - One launch, 24000 blocks: bids [0,4800) = compact pre-pass (b0 then b1),
//    bids [4800,24000) = main. Main blocks for batch b spin (acquire +
//    nanosleep) until that batch's 2400 pre blocks have released a counter.
//  - Dispatch is bid-ordered -> every pre CTA is resident-or-done before any
//    main CTA is resident -> deadlock-free. Pre-b1 DRAM work hides under
//    main-b0 L1-bound work.

namespace {
constexpr int B  = 2;
constexpr int H  = 160;
constexpr int W  = 192;
constexpr int D  = 160;
constexpr int WD = W * D;            // 30720
constexpr int N  = H * W * D;        // 4,915,200 per batch
constexpr int NT = B * N;            // 9,830,400 total voxels
constexpr int THREADS = 256;
constexpr int PRE_BLOCKS_PER_B = (N / 8) / THREADS;   // 2400
constexpr int PRE_BLOCKS  = 2 * PRE_BLOCKS_PER_B;     // 4800
constexpr int MAIN_BLOCKS = (NT / 2) / THREADS;       // 19200
constexpr int MAIN_PER_B  = MAIN_BLOCKS / 2;          // 9600
}

// Two fp16 copies of X channel-0, 19.7 MB each. Static scratch (no allocs).
__device__ __half g_even[NT];
__device__ __half g_odd[NT];
__device__ int    g_done[2];

// ---------------------------------------------------------------------------
__global__ void init_kernel() {
    g_done[0] = 0;
    g_done[1] = 0;
}

// ---------------------------------------------------------------------------
__device__ __forceinline__ float clampi_f(int v, int hi, int* out_i) {
    int c = v < 0 ? 0 : (v > hi ? hi : v);
    *out_i = c;
    return (float)c;
}

__device__ __forceinline__ float sample_one(int bN, int ix, int iy, int iz,
                                            float dx, float dy, float dz) {
    float x = (float)ix + dx;
    float y = (float)iy + dy;
    float z = (float)iz + dz;

    int x0i = (int)floorf(x);
    int y0i = (int)floorf(y);
    int z0i = (int)floorf(z);

    int x0, x1, y0, y1;
    float x0f = clampi_f(x0i,     W - 1, &x0);
    float x1f = clampi_f(x0i + 1, W - 1, &x1);
    float y0f = clampi_f(y0i,     H - 1, &y0);
    float y1f = clampi_f(y0i + 1, H - 1, &y1);
    float wx0 = x - x0f, wx1 = x1f - x;
    float wy0 = y - y0f, wy1 = y1f - y;

    // z degenerate (floor outside [0,D-2]) contributes exactly 0 in the ref
    // (wz0+wz1 = z1f-z0f = 0) -> zero the z-weights explicitly.
    bool zok  = (z0i >= 0) && (z0i < D - 1);
    int  zz   = zok ? z0i : 0;
    float wz0 = zok ? (z - (float)z0i)        : 0.0f;
    float wz1 = zok ? ((float)z0i + 1.0f - z) : 0.0f;

    const __half2* gz = (zz & 1) ? reinterpret_cast<const __half2*>(g_odd)
                                 : reinterpret_cast<const __half2*>(g_even);

    int i00 = bN + y0 * WD + x0 * D;
    int i01 = bN + y0 * WD + x1 * D;
    int i10 = bN + y1 * WD + x0 * D;
    int i11 = bN + y1 * WD + x1 * D;

    __half2 h00 = __ldg(&gz[(i00 + zz) >> 1]);   // .x=[z0], .y=[z0+1]
    __half2 h01 = __ldg(&gz[(i01 + zz) >> 1]);
    __half2 h10 = __ldg(&gz[(i10 + zz) >> 1]);
    __half2 h11 = __ldg(&gz[(i11 + zz) >> 1]);

    float c00 = wz1 * __half2float(h00.x) + wz0 * __half2float(h00.y);
    float c01 = wz1 * __half2float(h01.x) + wz0 * __half2float(h01.y);
    float c10 = wz1 * __half2float(h10.x) + wz0 * __half2float(h10.y);
    float c11 = wz1 * __half2float(h11.x) + wz0 * __half2float(h11.y);

    float c0 = wx1 * c00 + wx0 * c01;
    float c1 = wx1 * c10 + wx0 * c11;

    return wy1 * c0 + wy0 * c1;
}

// ---------------------------------------------------------------------------
__global__ void __launch_bounds__(THREADS)
fused_kernel(const float4* __restrict__ X4,
             const float2* __restrict__ def2,
             float2* __restrict__ out2) {
    int bid = blockIdx.x;
    int tid = threadIdx.x;

    if (bid < PRE_BLOCKS) {
        // ---------------- Pre-pass: compact X ch0 -> g_even / g_odd --------
        int i = bid * THREADS + tid;       // [0, NT/8)
        float4 a = X4[4 * i + 0];          // ch0 at .x,.z
        float4 b = X4[4 * i + 1];
        float4 c = X4[4 * i + 2];
        float4 d = X4[4 * i + 3];
        float extra = (i + 1 < NT / 8) ? X4[4 * i + 4].x : d.z;

        __half2 he[4], ho[4];
        he[0] = __floats2half2_rn(a.x, a.z);
        he[1] = __floats2half2_rn(b.x, b.z);
        he[2] = __floats2half2_rn(c.x, c.z);
        he[3] = __floats2half2_rn(d.x, d.z);
        ho[0] = __floats2half2_rn(a.z, b.x);
        ho[1] = __floats2half2_rn(b.z, c.x);
        ho[2] = __floats2half2_rn(c.z, d.x);
        ho[3] = __floats2half2_rn(d.z, extra);

        reinterpret_cast<uint4*>(g_even)[i] = *reinterpret_cast<uint4*>(he);
        reinterpret_cast<uint4*>(g_odd)[i]  = *reinterpret_cast<uint4*>(ho);

        __syncthreads();                   // all stores in this block issued
        if (tid == 0) {
            int b_idx = (bid < PRE_BLOCKS_PER_B) ? 0 : 1;
            int* ctr = &g_done[b_idx];
            // release: all prior stores visible before the increment is seen
            asm volatile("red.release.gpu.global.add.s32 [%0], 1;"
                         :: "l"(ctr) : "memory");
        }
        return;
    }

    // -------------------- Main: trilinear sampling -------------------------
    int j = bid - PRE_BLOCKS;              // [0, MAIN_BLOCKS)
    int b = (j < MAIN_PER_B) ? 0 : 1;

    // Wait until this batch's pre-pass is complete.
    if (tid == 0) {
        const int* ctr = &g_done[b];
        int v;
        do {
            asm volatile("ld.acquire.gpu.global.s32 %0, [%1];"
                         : "=r"(v) : "l"(ctr) : "memory");
            if (v < PRE_BLOCKS_PER_B) __nanosleep(128);
        } while (v < PRE_BLOCKS_PER_B);
    }
    __syncthreads();

    int t   = j * THREADS + tid;           // pair index [0, NT/2), grid exact
    int r2  = t * 2;
    int r   = r2 - b * N;
    int iy  = r / WD;
    int rem = r - iy * WD;
    int ix  = rem / D;
    int iz  = rem - ix * D;                // even; iz+1 < D

    float2 d0 = __ldcs(&def2[3 * t + 0]);  // (dxA, dyA)
    float2 d1 = __ldcs(&def2[3 * t + 1]);  // (dzA, dxB)
    float2 d2 = __ldcs(&def2[3 * t + 2]);  // (dyB, dzB)

    int bN = b * N;
    float2 o;
    o.x = sample_one(bN, ix, iy, iz,     d0.x, d0.y, d1.x);
    o.y = sample_one(bN, ix, iy, iz + 1, d1.y, d2.x, d2.y);

    __stcs(&out2[t], o);
}

extern "C" void kernel_launch(void* const* d_in, const int* in_sizes, int n_in,
                              void* d_out, int out_size) {
    const float* X   = (const float*)d_in[0];
    const float* def = (const float*)d_in[1];

    init_kernel<<<1, 1>>>();
    fused_kernel<<<PRE_BLOCKS + MAIN_BLOCKS, THREADS>>>(
        reinterpret_cast<const float4*>(X),
        reinterpret_cast<const float2*>(def),
        reinterpret_cast<float2*>(d_out));
}

// round 15
// speedup vs baseline: 1.2900x; 1.0208x over previous
#include <cuda_runtime.h>
#include <cuda_fp16.h>
#include <cstdint>

// SpatialDeformer3D: trilinear warp of X[...,0] by per-voxel deformation.
// Shapes fixed: B=2, H=160, W=192, D=160.
//
// R15 = R13 quad main (proven 51.8us) + rebuilt coalesced quad pre-pass.
//   g_quad[i], i = bN + y*WD + x*D + z, 4 halves (8 B, always aligned):
//     lo = (v(y,x,z),   v(y,x,z+1))
//     hi = (v(y,x+1,z), v(y,x+1,z+1))
//   -> 2 LDG.64 gathers/voxel in the main kernel.
// Pre-pass: block = (b, y, panel of 8 x-rows). Reads 9 contiguous rows of X
// (rows at fixed (b,y) are contiguous in memory) with fully-coalesced float4
// loads into smem (f32, z-padded), emits 8x160 quads as coalesced 8B stores.
// Traffic: 78.6*(9/8) read + 78.6 write = 167 MB (~26-28 us at DRAM floor),
// vs R13's 57 us (stride-4 float4 pattern broke coalescing).

namespace {
constexpr int B  = 2;
constexpr int H  = 160;
constexpr int W  = 192;
constexpr int D  = 160;
constexpr int WD = W * D;            // 30720
constexpr int N  = H * W * D;        // 4,915,200 per batch
constexpr int NT = B * N;            // 9,830,400 total voxels
constexpr int XP = 8;                // x-rows emitted per pre block
constexpr int PANELS = W / XP;       // 24
constexpr int ROW_F4 = D * 2 * 4 / 16;   // 80 float4 per (x)-row of X
constexpr int PRE_BLOCKS = B * H * PANELS;   // 7680
}

// Quad volume: 8 B per voxel = 78.6 MB. Static scratch (no allocs allowed).
__device__ uint2 g_quad[NT];

// ---------------------------------------------------------------------------
// Pre-pass: one block builds quads for 8 x-rows of one (b,y) plane.
__global__ void __launch_bounds__(256)
quad_pre_kernel(const float4* __restrict__ X4) {
    __shared__ float rows[XP + 1][D + 1];   // 9 x 161 f32 = 5796 B

    int bid = blockIdx.x;
    int p   = bid % PANELS;
    int y   = (bid / PANELS) % H;
    int b   = bid / (PANELS * H);
    int x0  = p * XP;

    // Load 9 input rows (x0..x0+8, x clamped at W-1; the clamped row only
    // feeds quads at x=W-1 which the main kernel never reads).
    int plane_base = (b * H + y) * W;   // row index base
    for (int t = threadIdx.x; t < (XP + 1) * ROW_F4; t += 256) {
        int r = t / ROW_F4;             // 0..8
        int c = t - r * ROW_F4;         // float4 within row
        int xr = x0 + r; if (xr > W - 1) xr = W - 1;
        float4 v = X4[(size_t)(plane_base + xr) * ROW_F4 + c];
        rows[r][2 * c]     = v.x;       // ch0 of voxel z=2c
        rows[r][2 * c + 1] = v.z;       // ch0 of voxel z=2c+1
    }
    __syncthreads();
    if (threadIdx.x < XP + 1)
        rows[threadIdx.x][D] = rows[threadIdx.x][D - 1];   // z pad (never read)
    __syncthreads();

    // Emit 8 x 160 quads, coalesced 8 B stores.
    uint2* dst = &g_quad[(size_t)(plane_base + x0) * D];
    for (int q = threadIdx.x; q < XP * D; q += 256) {
        int xr = q / D;
        int z  = q - xr * D;
        __half2 lo = __floats2half2_rn(rows[xr][z],     rows[xr][z + 1]);
        __half2 hi = __floats2half2_rn(rows[xr + 1][z], rows[xr + 1][z + 1]);
        uint2 val;
        val.x = *reinterpret_cast<uint32_t*>(&lo);
        val.y = *reinterpret_cast<uint32_t*>(&hi);
        dst[q] = val;
    }
}

// ---------------------------------------------------------------------------
__device__ __forceinline__ float clampi_f(int v, int hi, int* out_i) {
    int c = v < 0 ? 0 : (v > hi ? hi : v);
    *out_i = c;
    return (float)c;
}

__device__ __forceinline__ float sample_one(int bN, int ix, int iy, int iz,
                                            float dx, float dy, float dz) {
    float x = (float)ix + dx;
    float y = (float)iy + dy;
    float z = (float)iz + dz;

    int x0i = (int)floorf(x);
    int y0i = (int)floorf(y);
    int z0i = (int)floorf(z);

    // y: clamp both levels; degenerate y cancels algebraically.
    int y0, y1;
    float y0f = clampi_f(y0i,     H - 1, &y0);
    float y1f = clampi_f(y0i + 1, H - 1, &y1);
    float wy0 = y - y0f, wy1 = y1f - y;

    // x/z: quad requires base in [0, dim-2]; outside -> exact zero contribution
    // in the reference (w0+w1 = clip(hi)-clip(lo) = 0).
    bool xok  = (x0i >= 0) && (x0i < W - 1);
    int  xc   = xok ? x0i : 0;
    float wx0 = xok ? (x - (float)x0i)        : 0.0f;
    float wx1 = xok ? ((float)x0i + 1.0f - x) : 0.0f;

    bool zok  = (z0i >= 0) && (z0i < D - 1);
    int  zc   = zok ? z0i : 0;
    float wz0 = zok ? (z - (float)z0i)        : 0.0f;
    float wz1 = zok ? ((float)z0i + 1.0f - z) : 0.0f;

    int base = bN + xc * D + zc;
    uint2 q0 = __ldg(&g_quad[base + y0 * WD]);
    uint2 q1 = __ldg(&g_quad[base + y1 * WD]);

    __half2 lo0 = *reinterpret_cast<__half2*>(&q0.x);  // (v(x0,z0), v(x0,z1)) @ y0
    __half2 hi0 = *reinterpret_cast<__half2*>(&q0.y);  // (v(x1,z0), v(x1,z1)) @ y0
    __half2 lo1 = *reinterpret_cast<__half2*>(&q1.x);
    __half2 hi1 = *reinterpret_cast<__half2*>(&q1.y);

    float c00 = wz1 * __half2float(lo0.x) + wz0 * __half2float(lo0.y);
    float c01 = wz1 * __half2float(hi0.x) + wz0 * __half2float(hi0.y);
    float c10 = wz1 * __half2float(lo1.x) + wz0 * __half2float(lo1.y);
    float c11 = wz1 * __half2float(hi1.x) + wz0 * __half2float(hi1.y);

    float c0 = wx1 * c00 + wx0 * c01;   // y0 level
    float c1 = wx1 * c10 + wx0 * c11;   // y1 level

    return wy1 * c0 + wy0 * c1;
}

__global__ void __launch_bounds__(256)
deform3d_kernel(const float2* __restrict__ def2,
                float2* __restrict__ out2) {
    int t = blockIdx.x * blockDim.x + threadIdx.x;  // [0, NT/2)
    if (t >= NT / 2) return;

    int r2  = t * 2;
    int b   = r2 / N;
    int r   = r2 - b * N;
    int iy  = r / WD;
    int rem = r - iy * WD;
    int ix  = rem / D;
    int iz  = rem - ix * D;        // even; iz+1 < D

    float2 d0 = __ldcs(&def2[3 * t + 0]);   // (dxA, dyA)
    float2 d1 = __ldcs(&def2[3 * t + 1]);   // (dzA, dxB)
    float2 d2 = __ldcs(&def2[3 * t + 2]);   // (dyB, dzB)

    int bN = b * N;
    float2 o;
    o.x = sample_one(bN, ix, iy, iz,     d0.x, d0.y, d1.x);
    o.y = sample_one(bN, ix, iy, iz + 1, d1.y, d2.x, d2.y);

    __stcs(&out2[t], o);
}

extern "C" void kernel_launch(void* const* d_in, const int* in_sizes, int n_in,
                              void* d_out, int out_size) {
    const float* X   = (const float*)d_in[0];
    const float* def = (const float*)d_in[1];

    constexpr int threads = 256;
    constexpr int main_blocks = (NT / 2 + threads - 1) / threads;      // 19200

    quad_pre_kernel<<<PRE_BLOCKS, threads>>>(reinterpret_cast<const float4*>(X));
    deform3d_kernel<<<main_blocks, threads>>>(
        reinterpret_cast<const float2*>(def),
        reinterpret_cast<float2*>(d_out));
}